// round 3
// baseline (speedup 1.0000x reference)
#include <cuda_runtime.h>

// Fused CBF-QP controller, f32x2-packed math (FFMA2): one thread per (b,t) row.
// R2 bug fixed: state row stride is 64 bytes (4 x 16B vectors), not 32.

namespace {

constexpr int S_DIM = 16;
constexpr int H_DIM = 128;
constexpr int A_DIM = 4;
constexpr float QP_EPS = 1e-8f;

using u64 = unsigned long long;

__device__ __forceinline__ u64 pack2(float lo, float hi) {
    u64 r; asm("mov.b64 %0, {%1, %2};" : "=l"(r) : "f"(lo), "f"(hi)); return r;
}
__device__ __forceinline__ void unpack2(u64 v, float& lo, float& hi) {
    asm("mov.b64 {%0, %1}, %2;" : "=f"(lo), "=f"(hi) : "l"(v));
}
__device__ __forceinline__ u64 fma2(u64 a, u64 b, u64 c) {
    u64 d; asm("fma.rn.f32x2 %0, %1, %2, %3;" : "=l"(d) : "l"(a), "l"(b), "l"(c)); return d;
}
__device__ __forceinline__ u64 add2(u64 a, u64 b) {
    u64 d; asm("add.rn.f32x2 %0, %1, %2;" : "=l"(d) : "l"(a), "l"(b)); return d;
}
__device__ __forceinline__ u64 mul2(u64 a, u64 b) {
    u64 d; asm("mul.rn.f32x2 %0, %1, %2;" : "=l"(d) : "l"(a), "l"(b)); return d;
}

// Accurate fast tanh: tanh(x) = 1 - 2/(1+exp(2x)), MUFU.EX2 + MUFU.RCP, err ~1e-6.
__device__ __forceinline__ float fast_tanh(float x) {
    float z = fminf(fmaxf(x, -15.0f), 15.0f);
    float e; asm("ex2.approx.f32 %0, %1;" : "=f"(e) : "f"(z * 2.885390081777927f));
    float r; asm("rcp.approx.f32 %0, %1;" : "=f"(r) : "f"(e + 1.0f));
    return fmaf(-2.0f, r, 1.0f);
}

// dot(s, w) + bias with packed state s2[8] and 4 packed-pair weight loads.
__device__ __forceinline__ float dot16p(const u64* s2,
                                        ulonglong2 w0, ulonglong2 w1,
                                        ulonglong2 w2, ulonglong2 w3, float bias) {
    u64 a0 = mul2(s2[0], w0.x);
    u64 a1 = mul2(s2[4], w2.x);
    a0 = fma2(s2[1], w0.y, a0);
    a1 = fma2(s2[5], w2.y, a1);
    a0 = fma2(s2[2], w1.x, a0);
    a1 = fma2(s2[6], w3.x, a1);
    a0 = fma2(s2[3], w1.y, a0);
    a1 = fma2(s2[7], w3.y, a1);
    u64 sum = add2(a0, a1);
    float lo, hi; unpack2(sum, lo, hi);
    return bias + lo + hi;
}

__global__ void __launch_bounds__(256)
cbf_fused(const float* __restrict__ state,
          const float* __restrict__ Wc1, const float* __restrict__ bc1,
          const float* __restrict__ Wc2, const float* __restrict__ bc2,
          const float* __restrict__ Wh1, const float* __restrict__ bh1,
          const float* __restrict__ wh2, const float* __restrict__ bh2,
          const float* __restrict__ Wf,  const float* __restrict__ bf,
          const float* __restrict__ Wg,  const float* __restrict__ bg,
          float* __restrict__ out, int total)
{
    __shared__ float4 sWc1[H_DIM][4];        // Wc1^T
    __shared__ float4 sWh1[H_DIM][4];        // Wh1^T
    __shared__ float4 sWc2[H_DIM];
    __shared__ float4 sB[H_DIM];             // (bc1, bh1, wh2, 0)
    __shared__ float4 sWf[S_DIM][4];         // Wf^T
    __shared__ float4 sWg[S_DIM][S_DIM];     // native [k][s'] float4-over-a
    __shared__ float4 sbg[S_DIM];
    __shared__ float  sbf[S_DIM];
    __shared__ float  sbc2[A_DIM];
    __shared__ float  sbh2;

    const int tid = threadIdx.x;

    for (int idx = tid; idx < H_DIM * S_DIM; idx += blockDim.x) {
        const int j = idx >> 4, k = idx & 15;
        reinterpret_cast<float*>(sWc1)[idx] = Wc1[k * H_DIM + j];
        reinterpret_cast<float*>(sWh1)[idx] = Wh1[k * H_DIM + j];
    }
    for (int j = tid; j < H_DIM; j += blockDim.x) {
        sWc2[j] = reinterpret_cast<const float4*>(Wc2)[j];
        sB[j]   = make_float4(bc1[j], bh1[j], wh2[j], 0.0f);
    }
    for (int idx = tid; idx < S_DIM * S_DIM; idx += blockDim.x) {
        const int sp = idx >> 4, k = idx & 15;
        reinterpret_cast<float*>(sWf)[idx] = Wf[k * S_DIM + sp];
        reinterpret_cast<float4*>(sWg)[idx] = reinterpret_cast<const float4*>(Wg)[idx];
    }
    if (tid < S_DIM) { sbf[tid] = bf[tid]; sbg[tid] = reinterpret_cast<const float4*>(bg)[tid]; }
    if (tid < A_DIM) sbc2[tid] = bc2[tid];
    if (tid == 0)    sbh2 = bh2[0];
    __syncthreads();

    const int row = blockIdx.x * blockDim.x + tid;
    if (row >= total) return;

    // Packed state: 8 x f32x2 registers. Row stride = 16 floats = 64 bytes.
    u64 s2[8];
    {
        const ulonglong2* sp2 =
            reinterpret_cast<const ulonglong2*>(state + (size_t)row * S_DIM);
        const ulonglong2 a = sp2[0], b = sp2[1], c = sp2[2], d = sp2[3];
        s2[0] = a.x; s2[1] = a.y; s2[2] = b.x; s2[3] = b.y;
        s2[4] = c.x; s2[5] = c.y; s2[6] = d.x; s2[7] = d.y;
    }

    u64 uu01 = 0ull, uu23 = 0ull;   // controller output accumulators (packed)
    float hval = 0.0f;
    u64 dh2[8];
    #pragma unroll
    for (int m = 0; m < 8; ++m) dh2[m] = 0ull;

    #pragma unroll 4
    for (int j = 0; j < H_DIM; ++j) {
        const float4 bias = sB[j];

        // controller branch
        const ulonglong2* wc = reinterpret_cast<const ulonglong2*>(&sWc1[j][0]);
        const ulonglong2 w0 = wc[0], w1 = wc[1], w2 = wc[2], w3 = wc[3];
        const float t1 = fast_tanh(dot16p(s2, w0, w1, w2, w3, bias.x));
        const u64 t1p = pack2(t1, t1);
        const ulonglong2 wv2 = *reinterpret_cast<const ulonglong2*>(&sWc2[j]);
        uu01 = fma2(t1p, wv2.x, uu01);
        uu23 = fma2(t1p, wv2.y, uu23);

        // CBF branch (reuse loaded Wh1 pairs for the gradient accumulation)
        const ulonglong2* wh = reinterpret_cast<const ulonglong2*>(&sWh1[j][0]);
        const ulonglong2 h0 = wh[0], h1 = wh[1], h2 = wh[2], h3 = wh[3];
        const float t2 = fast_tanh(dot16p(s2, h0, h1, h2, h3, bias.y));
        hval = fmaf(t2, bias.z, hval);
        const float cj = fmaf(-t2 * t2, bias.z, bias.z);   // (1 - t2^2) * wh2[j]
        const u64 cj2 = pack2(cj, cj);
        dh2[0] = fma2(cj2, h0.x, dh2[0]); dh2[1] = fma2(cj2, h0.y, dh2[1]);
        dh2[2] = fma2(cj2, h1.x, dh2[2]); dh2[3] = fma2(cj2, h1.y, dh2[3]);
        dh2[4] = fma2(cj2, h2.x, dh2[4]); dh2[5] = fma2(cj2, h2.y, dh2[5]);
        dh2[6] = fma2(cj2, h3.x, dh2[6]); dh2[7] = fma2(cj2, h3.y, dh2[7]);
    }

    // Unpack gradient.
    float dh[16];
    #pragma unroll
    for (int m = 0; m < 8; ++m) unpack2(dh2[m], dh[2 * m], dh[2 * m + 1]);

    // right = h + dh . f
    float right = hval + sbh2;
    #pragma unroll
    for (int sp = 0; sp < S_DIM; ++sp) {
        const ulonglong2* wf = reinterpret_cast<const ulonglong2*>(&sWf[sp][0]);
        const float fv = dot16p(s2, wf[0], wf[1], wf[2], wf[3], sbf[sp]);
        right = fmaf(dh[sp], fv, right);
    }

    // Broadcast-packed state values for the g bilinear form.
    float sv[16];
    #pragma unroll
    for (int m = 0; m < 8; ++m) unpack2(s2[m], sv[2 * m], sv[2 * m + 1]);
    u64 sk2[16];
    #pragma unroll
    for (int k = 0; k < 16; ++k) sk2[k] = pack2(sv[k], sv[k]);

    // left[a] = -sum_s' dh[s'] * (state@Wg + bg)[s'][a]
    u64 l01 = 0ull, l23 = 0ull;
    #pragma unroll
    for (int sp = 0; sp < S_DIM; ++sp) {
        const ulonglong2 bgp = *reinterpret_cast<const ulonglong2*>(&sbg[sp]);
        u64 ax = bgp.x, ay = bgp.y;
        #pragma unroll
        for (int k = 0; k < S_DIM; ++k) {
            const ulonglong2 wg = *reinterpret_cast<const ulonglong2*>(&sWg[k][sp]);
            ax = fma2(sk2[k], wg.x, ax);
            ay = fma2(sk2[k], wg.y, ay);
        }
        const u64 nd = pack2(-dh[sp], -dh[sp]);
        l01 = fma2(nd, ax, l01);
        l23 = fma2(nd, ay, l23);
    }

    float l0, l1, l2, l3;
    unpack2(l01, l0, l1); unpack2(l23, l2, l3);
    float uu0, uu1, uu2, uu3;
    unpack2(uu01, uu0, uu1); unpack2(uu23, uu2, uu3);

    const float u0 = 2.0f * (uu0 + sbc2[0]);
    const float u1 = 2.0f * (uu1 + sbc2[1]);
    const float u2 = 2.0f * (uu2 + sbc2[2]);
    const float u3 = 2.0f * (uu3 + sbc2[3]);

    const float viol = l0*u0 + l1*u1 + l2*u2 + l3*u3 - right;
    const float den  = l0*l0 + l1*l1 + l2*l2 + l3*l3 + QP_EPS;
    const float lam  = viol > 0.0f ? (viol / den) : 0.0f;

    float4 res;
    res.x = fmaf(-lam, l0, u0);
    res.y = fmaf(-lam, l1, u1);
    res.z = fmaf(-lam, l2, u2);
    res.w = fmaf(-lam, l3, u3);
    reinterpret_cast<float4*>(out)[row] = res;
}

} // namespace

extern "C" void kernel_launch(void* const* d_in, const int* in_sizes, int n_in,
                              void* d_out, int out_size) {
    const float* state = (const float*)d_in[0];
    const float* Wc1   = (const float*)d_in[1];
    const float* bc1   = (const float*)d_in[2];
    const float* Wc2   = (const float*)d_in[3];
    const float* bc2   = (const float*)d_in[4];
    const float* Wh1   = (const float*)d_in[5];
    const float* bh1   = (const float*)d_in[6];
    const float* wh2   = (const float*)d_in[7];
    const float* bh2   = (const float*)d_in[8];
    const float* Wf    = (const float*)d_in[9];
    const float* bf    = (const float*)d_in[10];
    const float* Wg    = (const float*)d_in[11];
    const float* bg    = (const float*)d_in[12];

    const int total = in_sizes[0] / 16;
    const int threads = 256;
    const int blocks = (total + threads - 1) / threads;
    cbf_fused<<<blocks, threads>>>(state, Wc1, bc1, Wc2, bc2, Wh1, bh1, wh2, bh2,
                                   Wf, bf, Wg, bg, (float*)d_out, total);
}